// round 1
// baseline (speedup 1.0000x reference)
#include <cuda_runtime.h>
#include <cuda_bf16.h>

// Problem constants (HungarianMatcher_8650064134686)
#define BS   64
#define NQ   300
#define NC   2
#define TT   1280                 // total targets
#define ROWS (BS * NQ)            // 19200
#define ROWS_PER_BLOCK 16
#define THREADS 320               // TT / 4 targets per thread
#define GRID (ROWS / ROWS_PER_BLOCK)  // 1200

// cost = L1(span) - GIoU + (-prob_fg) + refdist
// GIoU = inter/uni - (enc - uni)/enc = inter/uni + uni/enc - 1
//      = (inter*enc + uni*uni) / (uni*enc) - 1        (single division)
// => cost = L1 + (1 - prob_fg + refdist) - num/den
//    row-constant rc = 1 - prob_fg + refdist computed once per row.

__global__ __launch_bounds__(THREADS)
void matcher_cost_kernel(const float* __restrict__ logits,   // [ROWS, 2]
                         const float* __restrict__ spans,    // [ROWS, 2] (cx, w)
                         const float* __restrict__ tgt,      // [TT, 2]   (cx, w)
                         const float* __restrict__ refp,     // [ROWS, 2]
                         float* __restrict__ out)            // [ROWS, TT]
{
    __shared__ float s_cx[ROWS_PER_BLOCK];
    __shared__ float s_w [ROWS_PER_BLOCK];
    __shared__ float s_x1[ROWS_PER_BLOCK];
    __shared__ float s_x2[ROWS_PER_BLOCK];
    __shared__ float s_rc[ROWS_PER_BLOCK];

    const int t    = threadIdx.x;
    const int row0 = blockIdx.x * ROWS_PER_BLOCK;

    // ---- per-row constants (first 16 threads) ----
    if (t < ROWS_PER_BLOCK) {
        const int r = row0 + t;
        const float cx = spans[2 * r + 0];
        const float w  = spans[2 * r + 1];
        const float x1 = cx - 0.5f * w;
        const float x2 = cx + 0.5f * w;
        const float l0 = logits[2 * r + 0];
        const float l1 = logits[2 * r + 1];
        // softmax prob of foreground class 0 (NC == 2)
        const float prob = 1.0f / (1.0f + __expf(l1 - l0));
        const float dx = x1 - refp[2 * r + 0];
        const float dy = x2 - refp[2 * r + 1];
        const float rd = sqrtf(fmaf(dx, dx, dy * dy));
        s_cx[t] = cx;
        s_w [t] = w;
        s_x1[t] = x1;
        s_x2[t] = x2;
        s_rc[t] = 1.0f - prob + rd;
    }

    // ---- per-thread targets: 4 consecutive targets, register-resident ----
    const float4* tg4 = reinterpret_cast<const float4*>(tgt);
    const float4 ta = tg4[2 * t + 0];   // (cx0, w0, cx1, w1)
    const float4 tb = tg4[2 * t + 1];   // (cx2, w2, cx3, w3)

    float tcx[4] = {ta.x, ta.z, tb.x, tb.z};
    float tw [4] = {ta.y, ta.w, tb.y, tb.w};
    float tx1[4], tx2[4];
#pragma unroll
    for (int j = 0; j < 4; ++j) {
        tx1[j] = tcx[j] - 0.5f * tw[j];
        tx2[j] = tcx[j] + 0.5f * tw[j];
    }

    __syncthreads();

    // ---- main loop over rows of this tile ----
#pragma unroll 2
    for (int rr = 0; rr < ROWS_PER_BLOCK; ++rr) {
        const float cx = s_cx[rr];
        const float w  = s_w [rr];
        const float x1 = s_x1[rr];
        const float x2 = s_x2[rr];
        const float rc = s_rc[rr];

        float res[4];
#pragma unroll
        for (int j = 0; j < 4; ++j) {
            // L1 span cost
            const float l1c = fabsf(cx - tcx[j]) + fabsf(w - tw[j]);
            // intersection
            const float lt    = fmaxf(x1, tx1[j]);
            const float rb    = fminf(x2, tx2[j]);
            const float inter = fmaxf(rb - lt, 0.0f);
            // union (w, tw > 0 => uni > 0)
            const float uni = (w + tw[j]) - inter;
            // enclosure
            const float le  = fminf(x1, tx1[j]);
            const float ri  = fmaxf(x2, tx2[j]);
            const float enc = ri - le;
            // folded GIoU fraction: num/den
            const float num = fmaf(uni, uni, inter * enc);
            const float den = uni * enc;
            res[j] = (l1c + rc) - __fdividef(num, den);
        }

        float4 o;
        o.x = res[0]; o.y = res[1]; o.z = res[2]; o.w = res[3];
        reinterpret_cast<float4*>(out + (size_t)(row0 + rr) * TT)[t] = o;
    }
}

extern "C" void kernel_launch(void* const* d_in, const int* in_sizes, int n_in,
                              void* d_out, int out_size)
{
    const float* pred_logits = (const float*)d_in[0];  // [BS, NQ, 2]
    const float* pred_spans  = (const float*)d_in[1];  // [BS, NQ, 2]
    const float* tgt_spans   = (const float*)d_in[2];  // [TT, 2]
    const float* ref_points  = (const float*)d_in[3];  // [BS, NQ, 2]
    float*       out         = (float*)d_out;          // [BS, NQ, TT]

    matcher_cost_kernel<<<GRID, THREADS>>>(pred_logits, pred_spans,
                                           tgt_spans, ref_points, out);
}

// round 4
// speedup vs baseline: 1.0638x; 1.0638x over previous
#include <cuda_runtime.h>
#include <cuda_bf16.h>
#include <cstdint>

// Problem constants (HungarianMatcher_8650064134686)
#define BS   64
#define NQ   300
#define TT   1280                     // total targets
#define ROWS (BS * NQ)                // 19200
#define ROWS_PER_BLOCK 16
#define THREADS 320                   // TT / 4 targets per thread
#define GRID (ROWS / ROWS_PER_BLOCK)  // 1200

typedef unsigned long long u64;

// ---- packed f32x2 helpers (Blackwell FADD2/FMUL2/FFMA2) ----
#define ADDX2(out, a, b) \
    asm("add.rn.f32x2 %0, %1, %2;" : "=l"(out) : "l"(a), "l"(b))
#define MULX2(out, a, b) \
    asm("mul.rn.f32x2 %0, %1, %2;" : "=l"(out) : "l"(a), "l"(b))
#define FMAX2(out, a, b, c) \
    asm("fma.rn.f32x2 %0, %1, %2, %3;" : "=l"(out) : "l"(a), "l"(b), "l"(c))
#define PACK2(out, lo, hi) \
    asm("mov.b64 %0, {%1, %2};" : "=l"(out) : "f"(lo), "f"(hi))
#define UNPACK2(lo, hi, in) \
    asm("mov.b64 {%0, %1}, %2;" : "=f"(lo), "=f"(hi) : "l"(in))
#define RCPA(out, in) \
    asm("rcp.approx.f32 %0, %1;" : "=f"(out) : "f"(in))

// Cost:
//   cost = L1(span) + (1 - prob_fg + refdist) - frac
//   frac = inter/uni + uni/enc = (I*E + U*U)/(U*E)   (scale-invariant)
// with S = w + tw, M = max(|w - tw|, 2|cx - tcx|):
//   I = max(S - M, 0)   (= 2*inter)
//   E = S + M           (= 2*enc)
//   U = 2S - I          (= 2*uni)

// One packed group = 2 targets. Inputs: row pairs (cx,cx),(w,w),(rc,rc) and
// per-target pairs (-tcx0,-tcx1), (-tw0,-tw1), (tw0,tw1), constant (-1,-1).
__device__ __forceinline__ void cost_pair(
    u64 cx2, u64 w2, u64 rc2,
    u64 ntcx, u64 ntw, u64 twp, u64 m1,
    float& o_lo, float& o_hi)
{
    u64 d2;  ADDX2(d2,  cx2, ntcx);   // cx - tcx
    u64 wd2; ADDX2(wd2, w2,  ntw);    // w - tw
    u64 S2;  ADDX2(S2,  w2,  twp);    // w + tw
    u64 dd2; ADDX2(dd2, d2,  d2);     // 2(cx - tcx)

    float d_lo, d_hi, wd_lo, wd_hi, dd_lo, dd_hi;
    UNPACK2(d_lo,  d_hi,  d2);
    UNPACK2(wd_lo, wd_hi, wd2);
    UNPACK2(dd_lo, dd_hi, dd2);

    // L1 span cost lanes (FADD with |.| operand modifiers)
    float l1_lo = fabsf(d_lo) + fabsf(wd_lo);
    float l1_hi = fabsf(d_hi) + fabsf(wd_hi);

    // nm = -M = min(-|wd|, -|2d|)  (single FMNMX with -|.| modifiers per lane)
    float nm_lo = fminf(-fabsf(wd_lo), -fabsf(dd_lo));
    float nm_hi = fminf(-fabsf(wd_hi), -fabsf(dd_hi));
    u64 nm2; PACK2(nm2, nm_lo, nm_hi);

    u64 i02; ADDX2(i02, S2, nm2);     // S - M
    float i0_lo, i0_hi;
    UNPACK2(i0_lo, i0_hi, i02);
    float I_lo = fmaxf(i0_lo, 0.0f);
    float I_hi = fmaxf(i0_hi, 0.0f);
    u64 I2; PACK2(I2, I_lo, I_hi);

    u64 SS2; ADDX2(SS2, S2, S2);      // 2S
    u64 U2;  FMAX2(U2, I2,  m1, SS2); // 2S - I
    u64 E2;  FMAX2(E2, nm2, m1, S2);  // S + M

    u64 p2;   MULX2(p2, I2, E2);      // I*E
    u64 num2; FMAX2(num2, U2, U2, p2);// U*U + I*E
    u64 den2; MULX2(den2, U2, E2);    // U*E

    u64 l12; PACK2(l12, l1_lo, l1_hi);
    u64 base2; ADDX2(base2, l12, rc2);

    float num_lo, num_hi, den_lo, den_hi, base_lo, base_hi;
    UNPACK2(num_lo, num_hi, num2);
    UNPACK2(den_lo, den_hi, den2);
    UNPACK2(base_lo, base_hi, base2);

    float r_lo; RCPA(r_lo, den_lo);
    float r_hi; RCPA(r_hi, den_hi);

    o_lo = fmaf(-num_lo, r_lo, base_lo);
    o_hi = fmaf(-num_hi, r_hi, base_hi);
}

__global__ __launch_bounds__(THREADS)
void matcher_cost_kernel(const float* __restrict__ logits,   // [ROWS, 2]
                         const float* __restrict__ spans,    // [ROWS, 2]
                         const float* __restrict__ tgt,      // [TT, 2]
                         const float* __restrict__ refp,     // [ROWS, 2]
                         float* __restrict__ out)            // [ROWS, TT]
{
    // Row constants pre-duplicated as 64-bit pairs: one LDS.64 = packed pair.
    __shared__ u64 s_cx2[ROWS_PER_BLOCK];
    __shared__ u64 s_w2 [ROWS_PER_BLOCK];
    __shared__ u64 s_rc2[ROWS_PER_BLOCK];

    const int t    = threadIdx.x;
    const int row0 = blockIdx.x * ROWS_PER_BLOCK;

    if (t < ROWS_PER_BLOCK) {
        const int r = row0 + t;
        const float cx = spans[2 * r + 0];
        const float w  = spans[2 * r + 1];
        const float x1 = cx - 0.5f * w;
        const float x2 = cx + 0.5f * w;
        const float l0 = logits[2 * r + 0];
        const float l1 = logits[2 * r + 1];
        const float prob = 1.0f / (1.0f + __expf(l1 - l0));  // softmax fg (NC=2)
        const float dx = x1 - refp[2 * r + 0];
        const float dy = x2 - refp[2 * r + 1];
        const float rd = sqrtf(fmaf(dx, dx, dy * dy));
        const float rc = 1.0f - prob + rd;
        u64 v;
        PACK2(v, cx, cx); s_cx2[t] = v;
        PACK2(v, w,  w ); s_w2 [t] = v;
        PACK2(v, rc, rc); s_rc2[t] = v;
    }

    // Per-thread targets: 4 consecutive targets as 2 packed pairs.
    const float4* tg4 = reinterpret_cast<const float4*>(tgt);
    const float4 ta = tg4[2 * t + 0];   // (cx0, w0, cx1, w1)
    const float4 tb = tg4[2 * t + 1];   // (cx2, w2, cx3, w3)

    u64 ntcx0, ntw0, tw0, ntcx1, ntw1, tw1, m1;
    {
        float a;
        a = -ta.x; float b0 = -ta.z; PACK2(ntcx0, a, b0);
        a = -ta.y; float b1 = -ta.w; PACK2(ntw0,  a, b1);
        PACK2(tw0, ta.y, ta.w);
        a = -tb.x; float b2 = -tb.z; PACK2(ntcx1, a, b2);
        a = -tb.y; float b3 = -tb.w; PACK2(ntw1,  a, b3);
        PACK2(tw1, tb.y, tb.w);
        const float mone = -1.0f;
        PACK2(m1, mone, mone);
    }

    __syncthreads();

    float4* orow = reinterpret_cast<float4*>(out) + (size_t)row0 * (TT / 4) + t;

#pragma unroll 2
    for (int rr = 0; rr < ROWS_PER_BLOCK; ++rr) {
        const u64 cx2 = s_cx2[rr];
        const u64 w2  = s_w2 [rr];
        const u64 rc2 = s_rc2[rr];

        float4 o;
        cost_pair(cx2, w2, rc2, ntcx0, ntw0, tw0, m1, o.x, o.y);
        cost_pair(cx2, w2, rc2, ntcx1, ntw1, tw1, m1, o.z, o.w);

        *orow = o;
        orow += TT / 4;
    }
}

extern "C" void kernel_launch(void* const* d_in, const int* in_sizes, int n_in,
                              void* d_out, int out_size)
{
    const float* pred_logits = (const float*)d_in[0];  // [BS, NQ, 2]
    const float* pred_spans  = (const float*)d_in[1];  // [BS, NQ, 2]
    const float* tgt_spans   = (const float*)d_in[2];  // [TT, 2]
    const float* ref_points  = (const float*)d_in[3];  // [BS, NQ, 2]
    float*       out         = (float*)d_out;          // [BS, NQ, TT]

    matcher_cost_kernel<<<GRID, THREADS>>>(pred_logits, pred_spans,
                                           tgt_spans, ref_points, out);
}

// round 5
// speedup vs baseline: 1.1969x; 1.1252x over previous
#include <cuda_runtime.h>
#include <cuda_bf16.h>
#include <cstdint>

// Problem constants (HungarianMatcher_8650064134686)
#define BS   64
#define NQ   300
#define TT   1280                     // total targets
#define ROWS (BS * NQ)                // 19200
#define ROWS_PER_BLOCK 16
#define THREADS 320                   // TT / 4 targets per thread
#define GRID (ROWS / ROWS_PER_BLOCK)  // 1200

typedef unsigned long long u64;

// ---- packed f32x2 helpers (Blackwell FADD2/FFMA2) ----
#define ADDX2(out, a, b) \
    asm("add.rn.f32x2 %0, %1, %2;" : "=l"(out) : "l"(a), "l"(b))
#define FMAX2(out, a, b, c) \
    asm("fma.rn.f32x2 %0, %1, %2, %3;" : "=l"(out) : "l"(a), "l"(b), "l"(c))
#define PACK2(out, lo, hi) \
    asm("mov.b64 %0, {%1, %2};" : "=l"(out) : "f"(lo), "f"(hi))
#define UNPACK2(lo, hi, in) \
    asm("mov.b64 {%0, %1}, %2;" : "=f"(lo), "=f"(hi) : "l"(in))
#define RCPA(out, in) \
    asm("rcp.approx.f32 %0, %1;" : "=f"(out) : "f"(in))

// 1-D GIoU closed form:
//   S = w + tw,  M = max(|w - tw|, 2|cx - tcx|)
//   inter_raw = (S - M)/2 (clamped), enclose = (S + M)/2
//   ==>  inter/uni + uni/enc  =  (S - M)/(S + M) + 1   in BOTH regimes
//   ==>  GIoU = (S - M)/(S + M)
// cost = |cx-tcx| + |w-tw| + (refdist - prob_fg) - (S - M)/(S + M)

// One packed group = 2 targets. rc2 = (rd - prob) duplicated.
__device__ __forceinline__ void cost_pair(
    u64 cx2, u64 w2, u64 rc2,
    u64 ntcx, u64 ntw, u64 twp, u64 m1,
    float& o_lo, float& o_hi)
{
    u64 d2;  ADDX2(d2,  cx2, ntcx);   // cx - tcx
    u64 wd2; ADDX2(wd2, w2,  ntw);    // w - tw
    u64 S2;  ADDX2(S2,  w2,  twp);    // w + tw
    u64 dd2; ADDX2(dd2, d2,  d2);     // 2(cx - tcx)

    float d_lo, d_hi, wd_lo, wd_hi, dd_lo, dd_hi;
    UNPACK2(d_lo,  d_hi,  d2);
    UNPACK2(wd_lo, wd_hi, wd2);
    UNPACK2(dd_lo, dd_hi, dd2);

    // L1 span cost (FADD with |.| operand modifiers)
    float l1_lo = fabsf(d_lo) + fabsf(wd_lo);
    float l1_hi = fabsf(d_hi) + fabsf(wd_hi);

    // nm = -M = min(-|wd|, -|2d|)  (single FMNMX with -|.| modifiers, alu pipe)
    float nm_lo = fminf(-fabsf(wd_lo), -fabsf(dd_lo));
    float nm_hi = fminf(-fabsf(wd_hi), -fabsf(dd_hi));

    u64 nm2;  PACK2(nm2, nm_lo, nm_hi);
    u64 num2; ADDX2(num2, S2, nm2);     // S - M
    u64 den2; FMAX2(den2, nm2, m1, S2); // S + M
    u64 l12;  PACK2(l12, l1_lo, l1_hi);
    u64 base2; ADDX2(base2, l12, rc2);  // L1 + rc

    float num_lo, num_hi, den_lo, den_hi, b_lo, b_hi;
    UNPACK2(num_lo, num_hi, num2);
    UNPACK2(den_lo, den_hi, den2);
    UNPACK2(b_lo,   b_hi,   base2);

    float r_lo; RCPA(r_lo, den_lo);
    float r_hi; RCPA(r_hi, den_hi);

    o_lo = fmaf(-num_lo, r_lo, b_lo);   // base - (S-M)/(S+M)
    o_hi = fmaf(-num_hi, r_hi, b_hi);
}

__global__ __launch_bounds__(THREADS)
void matcher_cost_kernel(const float* __restrict__ logits,   // [ROWS, 2]
                         const float* __restrict__ spans,    // [ROWS, 2]
                         const float* __restrict__ tgt,      // [TT, 2]
                         const float* __restrict__ refp,     // [ROWS, 2]
                         float* __restrict__ out)            // [ROWS, TT]
{
    // Row constants pre-duplicated: (cx,cx,w,w) as one LDS.128, (rc,rc) LDS.64.
    __shared__ float4 s_cxw[ROWS_PER_BLOCK];
    __shared__ u64    s_rc2[ROWS_PER_BLOCK];

    const int t    = threadIdx.x;
    const int row0 = blockIdx.x * ROWS_PER_BLOCK;

    if (t < ROWS_PER_BLOCK) {
        const int r = row0 + t;
        const float cx = spans[2 * r + 0];
        const float w  = spans[2 * r + 1];
        const float x1 = cx - 0.5f * w;
        const float x2 = cx + 0.5f * w;
        const float l0 = logits[2 * r + 0];
        const float l1 = logits[2 * r + 1];
        const float prob = 1.0f / (1.0f + __expf(l1 - l0));  // softmax fg (NC=2)
        const float dx = x1 - refp[2 * r + 0];
        const float dy = x2 - refp[2 * r + 1];
        const float rd = sqrtf(fmaf(dx, dx, dy * dy));
        const float rc = rd - prob;        // "+1" absorbed by GIoU identity
        float4 cw; cw.x = cx; cw.y = cx; cw.z = w; cw.w = w;
        s_cxw[t] = cw;
        u64 v; PACK2(v, rc, rc); s_rc2[t] = v;
    }

    // Per-thread targets: 4 consecutive targets as 2 packed pairs.
    const float4* tg4 = reinterpret_cast<const float4*>(tgt);
    const float4 ta = tg4[2 * t + 0];   // (cx0, w0, cx1, w1)
    const float4 tb = tg4[2 * t + 1];   // (cx2, w2, cx3, w3)

    u64 ntcx0, ntw0, tw0, ntcx1, ntw1, tw1, m1;
    {
        float a0 = -ta.x, b0 = -ta.z; PACK2(ntcx0, a0, b0);
        float a1 = -ta.y, b1 = -ta.w; PACK2(ntw0,  a1, b1);
        PACK2(tw0, ta.y, ta.w);
        float a2 = -tb.x, b2 = -tb.z; PACK2(ntcx1, a2, b2);
        float a3 = -tb.y, b3 = -tb.w; PACK2(ntw1,  a3, b3);
        PACK2(tw1, tb.y, tb.w);
        const float mone = -1.0f;
        PACK2(m1, mone, mone);
    }

    __syncthreads();

    float4* orow = reinterpret_cast<float4*>(out) + (size_t)row0 * (TT / 4) + t;

#pragma unroll 2
    for (int rr = 0; rr < ROWS_PER_BLOCK; ++rr) {
        const float4 cw = s_cxw[rr];          // LDS.128 -> (cx,cx,w,w)
        u64 cx2, w2;
        PACK2(cx2, cw.x, cw.y);
        PACK2(w2,  cw.z, cw.w);
        const u64 rc2 = s_rc2[rr];

        float4 o;
        cost_pair(cx2, w2, rc2, ntcx0, ntw0, tw0, m1, o.x, o.y);
        cost_pair(cx2, w2, rc2, ntcx1, ntw1, tw1, m1, o.z, o.w);

        *orow = o;
        orow += TT / 4;
    }
}

extern "C" void kernel_launch(void* const* d_in, const int* in_sizes, int n_in,
                              void* d_out, int out_size)
{
    const float* pred_logits = (const float*)d_in[0];  // [BS, NQ, 2]
    const float* pred_spans  = (const float*)d_in[1];  // [BS, NQ, 2]
    const float* tgt_spans   = (const float*)d_in[2];  // [TT, 2]
    const float* ref_points  = (const float*)d_in[3];  // [BS, NQ, 2]
    float*       out         = (float*)d_out;          // [BS, NQ, TT]

    matcher_cost_kernel<<<GRID, THREADS>>>(pred_logits, pred_spans,
                                           tgt_spans, ref_points, out);
}